// round 7
// baseline (speedup 1.0000x reference)
#include <cuda_runtime.h>
#include <math.h>
#include <float.h>
#include <stdint.h>

#define S   4096
#define MD  2048
#define E   32
#define CAP 256
#define CW_ELEMS ((size_t)S * E * CAP)   // 33554432

// ---------------- device scratch (no allocations allowed) ----------------
#define SPLITS 4
__device__ float g_part[SPLITS][S * E];   // split-K partial logits (2MB)

__device__ int   g_top_i1[S];
__device__ int   g_top_i2[S];
__device__ float g_top_v1[S];
__device__ float g_top_v2[S];
__device__ float g_top_g1[S];
__device__ float g_top_g2[S];
__device__ int   g_slot[S * 2];

#define NB2 128
__device__ float g_pgsum[NB2 * E];
__device__ int   g_pcnt[NB2 * E];

// ---------------- K1a: split-K GEMM (partial logits) ----------------------
#define K1_THREADS 128
#define KC 128
#define KSPAN (MD / SPLITS)   // 512
#define LD4 33                // float4 row stride (shifts banks)

__global__ __launch_bounds__(K1_THREADS)
void k1a_gemm(const float* __restrict__ x, const float* __restrict__ wg)
{
    __shared__ float4 xs[32 * LD4];
    __shared__ float4 ws[32 * LD4];

    const int split = blockIdx.x & (SPLITS - 1);
    const int tgrp  = blockIdx.x >> 2;
    const int tid = threadIdx.x;
    const int tx  = tid & 7;    // expert group (4 experts)
    const int ty  = tid >> 3;   // token group  (2 tokens), 0..15
    const int t0  = tgrp * 32;

    float acc[2][4];
#pragma unroll
    for (int i = 0; i < 2; i++)
#pragma unroll
        for (int j = 0; j < 4; j++) acc[i][j] = 0.f;

    const float4* x4 = (const float4*)x;
    const float4* w4 = (const float4*)wg;

    const int kbeg = split * KSPAN;
    for (int kc = kbeg; kc < kbeg + KSPAN; kc += KC) {
        const int kc4 = kc >> 2;
        for (int i = tid; i < 32 * 32; i += K1_THREADS) {
            int r = i >> 5, c = i & 31;
            xs[r * LD4 + c] = x4[(size_t)(t0 + r) * (MD / 4) + kc4 + c];
            ws[r * LD4 + c] = w4[(size_t)r       * (MD / 4) + kc4 + c];
        }
        __syncthreads();

#pragma unroll 8
        for (int k4 = 0; k4 < 32; k4++) {
            float4 a0 = xs[(2 * ty)     * LD4 + k4];
            float4 a1 = xs[(2 * ty + 1) * LD4 + k4];
#pragma unroll
            for (int j = 0; j < 4; j++) {
                float4 b = ws[(4 * tx + j) * LD4 + k4];
                acc[0][j] = fmaf(a0.x, b.x, fmaf(a0.y, b.y, fmaf(a0.z, b.z, fmaf(a0.w, b.w, acc[0][j]))));
                acc[1][j] = fmaf(a1.x, b.x, fmaf(a1.y, b.y, fmaf(a1.z, b.z, fmaf(a1.w, b.w, acc[1][j]))));
            }
        }
        __syncthreads();
    }

#pragma unroll
    for (int i = 0; i < 2; i++)
#pragma unroll
        for (int j = 0; j < 4; j++)
            g_part[split][(size_t)(t0 + 2 * ty + i) * E + (4 * tx + j)] = acc[i][j];
}

// ---------------- K1b: reduce splits + top2/softmax + partial sums --------
__global__ __launch_bounds__(1024)
void k1b_topk()
{
    const int warp = threadIdx.x >> 5;
    const int lane = threadIdx.x & 31;
    const int t = blockIdx.x * 32 + warp;
    const size_t o = (size_t)t * E + lane;

    float l = g_part[0][o] + g_part[1][o] + g_part[2][o] + g_part[3][o];

    // top-1 (tie -> lower index, matching jax.lax.top_k)
    float v1 = l; int i1 = lane;
#pragma unroll
    for (int off = 16; off; off >>= 1) {
        float ov = __shfl_xor_sync(0xffffffffu, v1, off);
        int   oi = __shfl_xor_sync(0xffffffffu, i1, off);
        if (ov > v1 || (ov == v1 && oi < i1)) { v1 = ov; i1 = oi; }
    }
    // top-2
    float l2 = (lane == i1) ? -FLT_MAX : l;
    float v2 = l2; int i2 = lane;
#pragma unroll
    for (int off = 16; off; off >>= 1) {
        float ov = __shfl_xor_sync(0xffffffffu, v2, off);
        int   oi = __shfl_xor_sync(0xffffffffu, i2, off);
        if (ov > v2 || (ov == v2 && oi < i2)) { v2 = ov; i2 = oi; }
    }

    // softmax over the 32 logits
    float p = expf(l - v1);
    float sum = p;
#pragma unroll
    for (int off = 16; off; off >>= 1) sum += __shfl_xor_sync(0xffffffffu, sum, off);
    float gate = p / sum;

    float g1v = __shfl_sync(0xffffffffu, gate, i1);
    float g2v = __shfl_sync(0xffffffffu, gate, i2);

    if (lane == 0) {
        g_top_i1[t] = i1;  g_top_i2[t] = i2;
        g_top_v1[t] = v1;  g_top_v2[t] = v2;
        g_top_g1[t] = g1v; g_top_g2[t] = g2v;
        g_slot[2 * t]     = -1;
        g_slot[2 * t + 1] = -1;
    }

    // deterministic per-block reduction of gate sums / counts
    __shared__ float gm[32][33];
    __shared__ int   im[32];
    gm[warp][lane] = gate;
    if (lane == 0) im[warp] = i1 | (i2 << 8);
    __syncthreads();

    if (warp == 0) {
        float s = 0.f; int c = 0;
#pragma unroll 8
        for (int w = 0; w < 32; w++) {
            s += gm[w][lane];
            int pk = im[w];
            c += ((pk & 255) == lane) + ((pk >> 8) == lane);
        }
        g_pgsum[blockIdx.x * E + lane] = s;
        g_pcnt [blockIdx.x * E + lane] = c;
    }
}

// ---------------- K3: per-expert capacity filter + slot assignment --------
__global__ __launch_bounds__(256)
void k3_capacity()
{
    const int e = blockIdx.x;
    __shared__ float vals[S];
    __shared__ int   s_cnt;
    __shared__ float s_thr;
    __shared__ int   warp_tot[8];
    __shared__ int   s_running;

    if (threadIdx.x == 0) { s_cnt = 0; s_running = 0; }
    __syncthreads();

    // gather positive selected logits for this expert
    for (int t = threadIdx.x; t < S; t += 256) {
        int i1 = g_top_i1[t], i2 = g_top_i2[t];
        float v; int hit = 0;
        if (i1 == e)      { v = g_top_v1[t]; hit = 1; }
        else if (i2 == e) { v = g_top_v2[t]; hit = 1; }
        else v = 0.f;
        if (hit && v > 0.f) {
            int p = atomicAdd(&s_cnt, 1);
            vals[p] = v;
        }
    }
    __syncthreads();

    int n = s_cnt;
    if (n <= CAP) {
        if (threadIdx.x == 0) s_thr = -FLT_MAX;
        __syncthreads();
    } else {
        int n2 = 1; while (n2 < n) n2 <<= 1;
        for (int i = n + threadIdx.x; i < n2; i += 256) vals[i] = -FLT_MAX;
        __syncthreads();
        // bitonic sort, descending
        for (int k = 2; k <= n2; k <<= 1) {
            for (int j = k >> 1; j > 0; j >>= 1) {
                for (int i = threadIdx.x; i < n2; i += 256) {
                    int ixj = i ^ j;
                    if (ixj > i) {
                        float a = vals[i], b = vals[ixj];
                        bool desc = ((i & k) == 0);
                        if (desc ? (a < b) : (a > b)) { vals[i] = b; vals[ixj] = a; }
                    }
                }
                __syncthreads();
            }
        }
        if (threadIdx.x == 0) s_thr = vals[CAP - 1];
        __syncthreads();
    }
    float thr = s_thr;

    // token-order scan: assign cumulative slots
    const int lane = threadIdx.x & 31;
    const int w    = threadIdx.x >> 5;
    for (int base = 0; base < S; base += 256) {
        int t = base + threadIdx.x;
        int i1 = g_top_i1[t], i2 = g_top_i2[t];
        int j = (i1 == e) ? 0 : ((i2 == e) ? 1 : -1);
        float v = (j == 0) ? g_top_v1[t] : ((j == 1) ? g_top_v2[t] : 0.f);
        int kept = (j >= 0 && v > 0.f && v >= thr) ? 1 : 0;

        unsigned bal = __ballot_sync(0xffffffffu, kept);
        int pre = __popc(bal & ((1u << lane) - 1u));
        if (lane == 31) warp_tot[w] = pre + kept;
        __syncthreads();

        int woff = 0;
#pragma unroll
        for (int ww = 0; ww < 8; ww++) woff += (ww < w) ? warp_tot[ww] : 0;
        int slot = s_running + woff + pre;
        if (kept) g_slot[2 * t + j] = slot;
        __syncthreads();

        if (threadIdx.x == 0) {
            int tot = 0;
#pragma unroll
            for (int ww = 0; ww < 8; ww++) tot += warp_tot[ww];
            s_running += tot;
        }
        __syncthreads();
    }
}

// ---------------- K4: scatter combine/dispatch + l_aux + exp_counts -------
__global__ __launch_bounds__(256)
void k4_final(float* __restrict__ laux, float* __restrict__ cw,
              float* __restrict__ dm,   float* __restrict__ ec)
{
    __shared__ float rs[8][32];
    __shared__ int   rc[8][32];

    if (blockIdx.x == 0) {
        int e  = threadIdx.x & 31;
        int ch = threadIdx.x >> 5;       // 0..7
        float s = 0.f; int c = 0;
        for (int b = ch; b < NB2; b += 8) {
            s += g_pgsum[b * E + e];
            c += g_pcnt [b * E + e];
        }
        rs[ch][e] = s; rc[ch][e] = c;
        __syncthreads();
        if (threadIdx.x < 32) {
            float st = 0.f; int ct = 0;
#pragma unroll
            for (int k = 0; k < 8; k++) { st += rs[k][threadIdx.x]; ct += rc[k][threadIdx.x]; }
            if (ec) ec[threadIdx.x] = (float)ct;
            float prod = (st / (float)S) * ((float)ct / (float)S);
#pragma unroll
            for (int off = 16; off; off >>= 1) prod += __shfl_xor_sync(0xffffffffu, prod, off);
            if (threadIdx.x == 0 && laux) laux[0] = prod * 16.0f;   // *E*E/K/E = *16
        }
    }

    int t = blockIdx.x * 256 + threadIdx.x;
    if (t >= S) return;

    int   i1 = g_top_i1[t], i2 = g_top_i2[t];
    float g1 = g_top_g1[t], g2 = g_top_g2[t];
    int   s1 = g_slot[2 * t], s2 = g_slot[2 * t + 1];
    bool  k1 = (s1 >= 0), k2 = (s2 >= 0);

    float denom = (k1 ? g1 : 0.f) + (k2 ? g2 : 0.f);
    if (denom <= 0.f) return;

    int c = (k1 ? s1 : 0) + (k2 ? s2 : 0);   // locations_s = SUM of slots (ref semantics)
    if (c >= CAP) return;                     // one_hot out of range -> all zeros

    if (k1 && cw) {
        size_t o = ((size_t)t * E + i1) * CAP + c;
        cw[o] = g1 / denom;
        if (dm) dm[o] = 1.0f;
    }
    if (k2 && cw) {
        size_t o = ((size_t)t * E + i2) * CAP + c;
        cw[o] = g2 / denom;
        if (dm) dm[o] = 1.0f;
    }
}

// ---------------- launch ---------------------------------------------------
extern "C" void kernel_launch(void* const* d_in, const int* in_sizes, int n_in,
                              void* d_out, int out_size)
{
    const float* x  = (const float*)d_in[0];
    const float* wg = (const float*)d_in[1];
    float* out = (float*)d_out;

    const long long CW = (long long)CW_ELEMS;
    float *laux = nullptr, *cw = nullptr, *dm = nullptr, *ec = nullptr;

    long long osz = (long long)out_size;
    if (osz == 1 + 2 * CW + 32) {
        laux = out;
        cw   = out + 1;
        dm   = out + 1 + CW;
        ec   = out + 1 + 2 * CW;
    } else if (osz == 2 * CW) {
        cw = out; dm = out + CW;
    } else if (osz == CW) {
        cw = out;
    } else {
        laux = out;
        cw   = out + 1;
        if (osz > 1 + CW)     dm = out + 1 + CW;
        if (osz > 1 + 2 * CW) ec = out + 1 + 2 * CW;
    }

    // One-time resource creation (host objects only; no device memory).
    static cudaStream_t s_side = nullptr;
    static cudaEvent_t  s_fork = nullptr, s_join = nullptr;
    if (s_side == nullptr) {
        cudaStreamCreateWithFlags(&s_side, cudaStreamNonBlocking);
        cudaEventCreateWithFlags(&s_fork, cudaEventDisableTiming);
        cudaEventCreateWithFlags(&s_join, cudaEventDisableTiming);
    }

    // Fork: big zero-fill of the output runs on a side stream, fully
    // overlapped with the gating pipeline (which doesn't touch `out`
    // until k4_final).
    cudaEventRecord(s_fork, 0);
    cudaStreamWaitEvent(s_side, s_fork, 0);
    cudaMemsetAsync(out, 0, (size_t)osz * sizeof(float), s_side);
    cudaEventRecord(s_join, s_side);

    // Main pipeline (independent of `out`).
    k1a_gemm<<<128 * SPLITS, K1_THREADS>>>(x, wg);
    k1b_topk<<<NB2, 1024>>>();
    k3_capacity<<<E, 256>>>();

    // Join: k4 writes into `out`, so it must wait for the memset too.
    cudaStreamWaitEvent(0, s_join, 0);
    k4_final<<<(S + 255) / 256, 256>>>(laux, cw, dm, ec);
}

// round 8
// speedup vs baseline: 1.2987x; 1.2987x over previous
#include <cuda_runtime.h>
#include <math.h>
#include <float.h>
#include <stdint.h>

#define S   4096
#define MD  2048
#define E   32
#define CAP 256
#define ROW (E * CAP)                    // 8192 floats per token row-group
#define CW_ELEMS ((size_t)S * E * CAP)   // 33554432

// ---------------- device scratch (no allocations allowed) ----------------
#define SPLITS 4
__device__ float g_part[SPLITS][S * E];   // split-K partial logits (2MB)

__device__ int   g_top_i1[S];
__device__ int   g_top_i2[S];
__device__ float g_top_v1[S];
__device__ float g_top_v2[S];
__device__ float g_top_g1[S];
__device__ float g_top_g2[S];
__device__ int   g_slot[S * 2];

#define NB2 128
__device__ float g_pgsum[NB2 * E];
__device__ int   g_pcnt[NB2 * E];
__device__ float g_laux;
__device__ float g_ec[E];

// ---------------- K1a: split-K GEMM (partial logits) ----------------------
#define K1_THREADS 128
#define KC 128
#define KSPAN (MD / SPLITS)   // 512
#define LD4 33                // float4 row stride (shifts banks)

__global__ __launch_bounds__(K1_THREADS)
void k1a_gemm(const float* __restrict__ x, const float* __restrict__ wg)
{
    __shared__ float4 xs[32 * LD4];
    __shared__ float4 ws[32 * LD4];

    const int split = blockIdx.x & (SPLITS - 1);
    const int tgrp  = blockIdx.x >> 2;
    const int tid = threadIdx.x;
    const int tx  = tid & 7;    // expert group (4 experts)
    const int ty  = tid >> 3;   // token group  (2 tokens), 0..15
    const int t0  = tgrp * 32;

    float acc[2][4];
#pragma unroll
    for (int i = 0; i < 2; i++)
#pragma unroll
        for (int j = 0; j < 4; j++) acc[i][j] = 0.f;

    const float4* x4 = (const float4*)x;
    const float4* w4 = (const float4*)wg;

    const int kbeg = split * KSPAN;
    for (int kc = kbeg; kc < kbeg + KSPAN; kc += KC) {
        const int kc4 = kc >> 2;
        for (int i = tid; i < 32 * 32; i += K1_THREADS) {
            int r = i >> 5, c = i & 31;
            xs[r * LD4 + c] = x4[(size_t)(t0 + r) * (MD / 4) + kc4 + c];
            ws[r * LD4 + c] = w4[(size_t)r       * (MD / 4) + kc4 + c];
        }
        __syncthreads();

#pragma unroll 8
        for (int k4 = 0; k4 < 32; k4++) {
            float4 a0 = xs[(2 * ty)     * LD4 + k4];
            float4 a1 = xs[(2 * ty + 1) * LD4 + k4];
#pragma unroll
            for (int j = 0; j < 4; j++) {
                float4 b = ws[(4 * tx + j) * LD4 + k4];
                acc[0][j] = fmaf(a0.x, b.x, fmaf(a0.y, b.y, fmaf(a0.z, b.z, fmaf(a0.w, b.w, acc[0][j]))));
                acc[1][j] = fmaf(a1.x, b.x, fmaf(a1.y, b.y, fmaf(a1.z, b.z, fmaf(a1.w, b.w, acc[1][j]))));
            }
        }
        __syncthreads();
    }

#pragma unroll
    for (int i = 0; i < 2; i++)
#pragma unroll
        for (int j = 0; j < 4; j++)
            g_part[split][(size_t)(t0 + 2 * ty + i) * E + (4 * tx + j)] = acc[i][j];
}

// ---------------- K1b: reduce splits + top2/softmax + partial sums --------
__global__ __launch_bounds__(1024)
void k1b_topk()
{
    const int warp = threadIdx.x >> 5;
    const int lane = threadIdx.x & 31;
    const int t = blockIdx.x * 32 + warp;
    const size_t o = (size_t)t * E + lane;

    float l = g_part[0][o] + g_part[1][o] + g_part[2][o] + g_part[3][o];

    // top-1 (tie -> lower index, matching jax.lax.top_k)
    float v1 = l; int i1 = lane;
#pragma unroll
    for (int off = 16; off; off >>= 1) {
        float ov = __shfl_xor_sync(0xffffffffu, v1, off);
        int   oi = __shfl_xor_sync(0xffffffffu, i1, off);
        if (ov > v1 || (ov == v1 && oi < i1)) { v1 = ov; i1 = oi; }
    }
    // top-2
    float l2 = (lane == i1) ? -FLT_MAX : l;
    float v2 = l2; int i2 = lane;
#pragma unroll
    for (int off = 16; off; off >>= 1) {
        float ov = __shfl_xor_sync(0xffffffffu, v2, off);
        int   oi = __shfl_xor_sync(0xffffffffu, i2, off);
        if (ov > v2 || (ov == v2 && oi < i2)) { v2 = ov; i2 = oi; }
    }

    // softmax over the 32 logits
    float p = expf(l - v1);
    float sum = p;
#pragma unroll
    for (int off = 16; off; off >>= 1) sum += __shfl_xor_sync(0xffffffffu, sum, off);
    float gate = p / sum;

    float g1v = __shfl_sync(0xffffffffu, gate, i1);
    float g2v = __shfl_sync(0xffffffffu, gate, i2);

    if (lane == 0) {
        g_top_i1[t] = i1;  g_top_i2[t] = i2;
        g_top_v1[t] = v1;  g_top_v2[t] = v2;
        g_top_g1[t] = g1v; g_top_g2[t] = g2v;
        g_slot[2 * t]     = -1;
        g_slot[2 * t + 1] = -1;
    }

    // deterministic per-block reduction of gate sums / counts
    __shared__ float gm[32][33];
    __shared__ int   im[32];
    gm[warp][lane] = gate;
    if (lane == 0) im[warp] = i1 | (i2 << 8);
    __syncthreads();

    if (warp == 0) {
        float s = 0.f; int c = 0;
#pragma unroll 8
        for (int w = 0; w < 32; w++) {
            s += gm[w][lane];
            int pk = im[w];
            c += ((pk & 255) == lane) + ((pk >> 8) == lane);
        }
        g_pgsum[blockIdx.x * E + lane] = s;
        g_pcnt [blockIdx.x * E + lane] = c;
    }
}

// ---------------- K3: capacity filter + slot assignment (+laux reduce) ----
__global__ __launch_bounds__(256)
void k3_capacity()
{
    if (blockIdx.x == E) {
        // reduce partial gate sums / counts -> g_laux, g_ec
        __shared__ float rs[8][32];
        __shared__ int   rc[8][32];
        int e  = threadIdx.x & 31;
        int ch = threadIdx.x >> 5;
        float s = 0.f; int c = 0;
        for (int b = ch; b < NB2; b += 8) {
            s += g_pgsum[b * E + e];
            c += g_pcnt [b * E + e];
        }
        rs[ch][e] = s; rc[ch][e] = c;
        __syncthreads();
        if (threadIdx.x < 32) {
            float st = 0.f; int ct = 0;
#pragma unroll
            for (int k = 0; k < 8; k++) { st += rs[k][threadIdx.x]; ct += rc[k][threadIdx.x]; }
            g_ec[threadIdx.x] = (float)ct;
            float prod = (st / (float)S) * ((float)ct / (float)S);
#pragma unroll
            for (int off = 16; off; off >>= 1) prod += __shfl_xor_sync(0xffffffffu, prod, off);
            if (threadIdx.x == 0) g_laux = prod * 16.0f;   // *E*E/K/E = *16
        }
        return;
    }

    const int e = blockIdx.x;
    __shared__ float vals[S];
    __shared__ int   s_cnt;
    __shared__ float s_thr;
    __shared__ int   warp_tot[8];
    __shared__ int   s_running;

    if (threadIdx.x == 0) { s_cnt = 0; s_running = 0; }
    __syncthreads();

    // gather positive selected logits for this expert
    for (int t = threadIdx.x; t < S; t += 256) {
        int i1 = g_top_i1[t], i2 = g_top_i2[t];
        float v; int hit = 0;
        if (i1 == e)      { v = g_top_v1[t]; hit = 1; }
        else if (i2 == e) { v = g_top_v2[t]; hit = 1; }
        else v = 0.f;
        if (hit && v > 0.f) {
            int p = atomicAdd(&s_cnt, 1);
            vals[p] = v;
        }
    }
    __syncthreads();

    int n = s_cnt;
    if (n <= CAP) {
        if (threadIdx.x == 0) s_thr = -FLT_MAX;
        __syncthreads();
    } else {
        int n2 = 1; while (n2 < n) n2 <<= 1;
        for (int i = n + threadIdx.x; i < n2; i += 256) vals[i] = -FLT_MAX;
        __syncthreads();
        // bitonic sort, descending
        for (int k = 2; k <= n2; k <<= 1) {
            for (int j = k >> 1; j > 0; j >>= 1) {
                for (int i = threadIdx.x; i < n2; i += 256) {
                    int ixj = i ^ j;
                    if (ixj > i) {
                        float a = vals[i], b = vals[ixj];
                        bool desc = ((i & k) == 0);
                        if (desc ? (a < b) : (a > b)) { vals[i] = b; vals[ixj] = a; }
                    }
                }
                __syncthreads();
            }
        }
        if (threadIdx.x == 0) s_thr = vals[CAP - 1];
        __syncthreads();
    }
    float thr = s_thr;

    // token-order scan: assign cumulative slots
    const int lane = threadIdx.x & 31;
    const int w    = threadIdx.x >> 5;
    for (int base = 0; base < S; base += 256) {
        int t = base + threadIdx.x;
        int i1 = g_top_i1[t], i2 = g_top_i2[t];
        int j = (i1 == e) ? 0 : ((i2 == e) ? 1 : -1);
        float v = (j == 0) ? g_top_v1[t] : ((j == 1) ? g_top_v2[t] : 0.f);
        int kept = (j >= 0 && v > 0.f && v >= thr) ? 1 : 0;

        unsigned bal = __ballot_sync(0xffffffffu, kept);
        int pre = __popc(bal & ((1u << lane) - 1u));
        if (lane == 31) warp_tot[w] = pre + kept;
        __syncthreads();

        int woff = 0;
#pragma unroll
        for (int ww = 0; ww < 8; ww++) woff += (ww < w) ? warp_tot[ww] : 0;
        int slot = s_running + woff + pre;
        if (kept) g_slot[2 * t + j] = slot;
        __syncthreads();

        if (threadIdx.x == 0) {
            int tot = 0;
#pragma unroll
            for (int ww = 0; ww < 8; ww++) tot += warp_tot[ww];
            s_running += tot;
        }
        __syncthreads();
    }
}

// ---------------- K4: fused zero-fill + scatter ---------------------------
#define CHUNK 65536LL   // floats per block (256KB)

__device__ __forceinline__ void patch_token(int t, float* out,
                                            long long lo, long long hi,
                                            long long base, bool weighted)
{
    if (t < 0 || t >= S) return;
    int   i1 = g_top_i1[t], i2 = g_top_i2[t];
    float g1 = g_top_g1[t], g2 = g_top_g2[t];
    int   s1 = g_slot[2 * t], s2 = g_slot[2 * t + 1];
    bool  k1 = (s1 >= 0), k2 = (s2 >= 0);

    float denom = (k1 ? g1 : 0.f) + (k2 ? g2 : 0.f);
    if (denom <= 0.f) return;
    int c = (k1 ? s1 : 0) + (k2 ? s2 : 0);   // locations_s = SUM of slots
    if (c >= CAP) return;                     // one_hot out of range

    if (k1) {
        long long idx = base + ((long long)t * E + i1) * CAP + c;
        if (idx >= lo && idx < hi) out[idx] = weighted ? (g1 / denom) : 1.0f;
    }
    if (k2) {
        long long idx = base + ((long long)t * E + i2) * CAP + c;
        if (idx >= lo && idx < hi) out[idx] = weighted ? (g2 / denom) : 1.0f;
    }
}

__global__ __launch_bounds__(256)
void k4_fill_scatter(float* __restrict__ out, long long osz,
                     long long o_laux, long long o_cw,
                     long long o_dm,   long long o_ec)
{
    const long long lo = (long long)blockIdx.x * CHUNK;
    const long long hi = min(lo + CHUNK, osz);

    // ---- streaming zero-fill of [lo, hi) ----
    {
        long long lo4 = lo >> 2;            // lo is CHUNK-aligned (mult of 4)
        long long hi4 = hi >> 2;            // floor
        float4 z = make_float4(0.f, 0.f, 0.f, 0.f);
        float4* o4 = (float4*)out;
        for (long long i = lo4 + threadIdx.x; i < hi4; i += 256)
            __stcs(o4 + i, z);
        if (hi == osz) {                    // scalar tail
            for (long long i = (hi4 << 2) + threadIdx.x; i < osz; i += 256)
                out[i] = 0.f;
        }
    }
    __syncthreads();

    // ---- patch nonzeros that land inside [lo, hi) ----
    const int tid = threadIdx.x;

    // combine_weights section
    if (o_cw >= 0 && tid < 16) {
        long long sec_lo = o_cw, sec_hi = o_cw + (long long)CW_ELEMS;
        if (hi > sec_lo && lo < sec_hi) {
            long long a = lo > sec_lo ? lo : sec_lo;
            long long b = hi < sec_hi ? hi : sec_hi;
            long long tmin = (a - sec_lo) / ROW;
            long long tmax = (b - 1 - sec_lo) / ROW;
            long long t = tmin + tid;
            if (t <= tmax) patch_token((int)t, out, lo, hi, sec_lo, true);
        }
    }
    // dispatch_mask section
    if (o_dm >= 0 && tid >= 16 && tid < 32) {
        long long sec_lo = o_dm, sec_hi = o_dm + (long long)CW_ELEMS;
        if (hi > sec_lo && lo < sec_hi) {
            long long a = lo > sec_lo ? lo : sec_lo;
            long long b = hi < sec_hi ? hi : sec_hi;
            long long tmin = (a - sec_lo) / ROW;
            long long tmax = (b - 1 - sec_lo) / ROW;
            long long t = tmin + (tid - 16);
            if (t <= tmax) patch_token((int)t, out, lo, hi, sec_lo, false);
        }
    }
    // l_aux scalar
    if (tid == 32 && o_laux >= lo && o_laux < hi) out[o_laux] = g_laux;
    // exp_counts
    if (o_ec >= 0 && tid >= 64 && tid < 96) {
        int e = tid - 64;
        long long idx = o_ec + e;
        if (idx >= lo && idx < hi) out[idx] = g_ec[e];
    }
}

// ---------------- launch ---------------------------------------------------
extern "C" void kernel_launch(void* const* d_in, const int* in_sizes, int n_in,
                              void* d_out, int out_size)
{
    const float* x  = (const float*)d_in[0];
    const float* wg = (const float*)d_in[1];
    float* out = (float*)d_out;

    const long long CW = (long long)CW_ELEMS;
    long long o_laux = -1, o_cw = -1, o_dm = -1, o_ec = -1;

    long long osz = (long long)out_size;
    if (osz == 1 + 2 * CW + 32) {
        o_laux = 0;
        o_cw   = 1;
        o_dm   = 1 + CW;
        o_ec   = 1 + 2 * CW;
    } else if (osz == 2 * CW) {
        o_cw = 0; o_dm = CW;
    } else if (osz == CW) {
        o_cw = 0;
    } else {
        o_laux = 0;
        o_cw   = 1;
        if (osz > 1 + CW)     o_dm = 1 + CW;
        if (osz > 1 + 2 * CW) o_ec = 1 + 2 * CW;
    }

    k1a_gemm<<<128 * SPLITS, K1_THREADS>>>(x, wg);
    k1b_topk<<<NB2, 1024>>>();
    k3_capacity<<<E + 1, 256>>>();

    int fill_blocks = (int)((osz + CHUNK - 1) / CHUNK);
    k4_fill_scatter<<<fill_blocks, 256>>>(out, osz, o_laux, o_cw, o_dm, o_ec);
}